// round 7
// baseline (speedup 1.0000x reference)
#include <cuda_runtime.h>
#include <math.h>

#define NUM_INITS   64
#define BATCH_N     128
#define TOTAL_P     18378
#define OFF_W1      0
#define OFF_B1      400
#define OFF_W2      416
#define OFF_B2      13216
#define OFF_WD      13248
#define OFF_BD      18368

// a1 padded layout: [img][ci][row(12) x stride 20] -> conflict-free conv2 row loads
#define A1_RS   20
#define A1_CS   240          // 12 rows * 20
#define A1_IS   3840         // 16 ch * 240

__global__ __launch_bounds__(256, 3)
void ensemble_lenet_kernel(const float* __restrict__ params,
                           const float* __restrict__ batch,
                           float* __restrict__ out)
{
    __shared__ float s_w1[400];
    __shared__ float s_b1[16];
    __shared__ float s_b2[32];
    __shared__ __align__(16) float s_a1[2 * A1_IS];   // 7680
    __shared__ __align__(16) float s_u[3200];         // union: img(1568) / w2 chunk(3200) / a2(1024)
    __shared__ float s_dot[2][16];

    const int blk   = blockIdx.x;
    const int init  = blk >> 6;
    const int npair = blk & 63;
    const int t     = threadIdx.x;
    const int img   = t >> 7;        // 0,1
    const int tl    = t & 127;

    const float* __restrict__ P = params + init * TOTAL_P;

    // ---------- stage 2 images (contiguous) + conv1 params ----------
    {
        const float* ib = batch + (npair * 2) * 784;
        for (int idx = t; idx < 1568; idx += 256) s_u[idx] = ib[idx];
        for (int idx = t; idx < 400;  idx += 256) s_w1[idx] = P[idx];
        if (t < 16) s_b1[t] = P[OFF_B1 + t];
        if (t < 32) s_b2[t] = P[OFF_B2 + t];
    }
    __syncthreads();

    // ---------- conv1 + relu + pool ----------
    // 128 threads per image: 16 channels x 8 lanes; 18 pooled positions per lane.
    {
        const int co = (tl >> 3) & 15;
        const int l8 = tl & 7;
        float w1r[25];
        #pragma unroll
        for (int q = 0; q < 25; q++) w1r[q] = s_w1[co * 25 + q];
        const float b1 = s_b1[co];
        const float* imgp = s_u + img * 784;
        float* a1p = s_a1 + img * A1_IS + co * A1_CS;

        #pragma unroll 2
        for (int k = 0; k < 18; k++) {
            const int idx = l8 + (k << 3);       // 0..143
            const int py = idx / 12;
            const int px = idx - py * 12;
            const int iy = py * 2, ix = px * 2;

            float a00 = b1, a01 = b1, a10 = b1, a11 = b1;
            #pragma unroll
            for (int r = 0; r < 6; r++) {
                const float2* rp = (const float2*)(imgp + (iy + r) * 28 + ix);
                const float2 v0 = rp[0], v1 = rp[1], v2 = rp[2];
                float row[6];
                row[0]=v0.x; row[1]=v0.y; row[2]=v1.x; row[3]=v1.y; row[4]=v2.x; row[5]=v2.y;
                if (r < 5) {
                    #pragma unroll
                    for (int dx = 0; dx < 5; dx++) {
                        const float w = w1r[r * 5 + dx];
                        a00 = fmaf(row[dx],     w, a00);
                        a01 = fmaf(row[dx + 1], w, a01);
                    }
                }
                if (r >= 1) {
                    #pragma unroll
                    for (int dx = 0; dx < 5; dx++) {
                        const float w = w1r[(r - 1) * 5 + dx];
                        a10 = fmaf(row[dx],     w, a10);
                        a11 = fmaf(row[dx + 1], w, a11);
                    }
                }
            }
            const float m = fmaxf(fmaxf(a00, a01), fmaxf(a10, a11));
            a1p[py * A1_RS + px] = fmaxf(m, 0.0f);
        }
    }
    __syncthreads();

    // ---------- conv2 + relu + pool:  2 output channels per thread ----------
    // thread: c2p = channel pair (c2p, c2p+16), j = output row 0..7
    const int c2p = (tl >> 3) & 15;
    const int j   = tl & 7;
    float acc0[8], acc1[8];
    {
        const float b20 = s_b2[c2p];
        const float b21 = s_b2[c2p + 16];
        #pragma unroll
        for (int x = 0; x < 8; x++) { acc0[x] = b20; acc1[x] = b21; }
    }

    for (int cb = 0; cb < 4; cb++) {
        // stage weight chunk (4 input channels), pair-interleaved:
        // s_u[((cil*25+tap)*16 + cp)*2 + h] = w2[cp + 16h][cb*4+cil][tap]
        for (int idx = t; idx < 3200; idx += 256) {
            const int h   = idx & 1;
            const int cp  = (idx >> 1) & 15;
            const int rem = idx >> 5;            // cil*25 + tap
            const int cil = rem / 25;
            const int tap = rem - cil * 25;
            s_u[idx] = P[OFF_W2 + ((cp + (h << 4)) * 16 + (cb * 4 + cil)) * 25 + tap];
        }
        __syncthreads();

        for (int cil = 0; cil < 4; cil++) {
            const float* abase = s_a1 + img * A1_IS + (cb * 4 + cil) * A1_CS;
            const float2* wbase = (const float2*)(s_u) + (cil * 25) * 16 + c2p;
            #pragma unroll
            for (int dy = 0; dy < 5; dy++) {
                const float4* rp = (const float4*)(abase + (j + dy) * A1_RS);
                const float4 v0 = rp[0], v1 = rp[1], v2 = rp[2];
                float a[12];
                a[0]=v0.x; a[1]=v0.y; a[2]=v0.z; a[3]=v0.w;
                a[4]=v1.x; a[5]=v1.y; a[6]=v1.z; a[7]=v1.w;
                a[8]=v2.x; a[9]=v2.y; a[10]=v2.z; a[11]=v2.w;
                const float2* wp = wbase + (dy * 5) * 16;
                #pragma unroll
                for (int dx = 0; dx < 5; dx++) {
                    const float2 w = wp[dx * 16];
                    #pragma unroll
                    for (int x = 0; x < 8; x++) {
                        acc0[x] = fmaf(a[x + dx], w.x, acc0[x]);
                        acc1[x] = fmaf(a[x + dx], w.y, acc1[x]);
                    }
                }
            }
        }
        __syncthreads();
    }

    // pool rows pairwise via shuffle (lane^1 = row j^1, same c2p/img), write a2 into union
    {
        float m0[8], m1[8];
        #pragma unroll
        for (int x = 0; x < 8; x++) {
            m0[x] = fmaxf(acc0[x], __shfl_xor_sync(0xFFFFFFFFu, acc0[x], 1));
            m1[x] = fmaxf(acc1[x], __shfl_xor_sync(0xFFFFFFFFu, acc1[x], 1));
        }
        if ((j & 1) == 0) {
            const int py = j >> 1;
            float* a2 = s_u + img * 512;
            #pragma unroll
            for (int px = 0; px < 4; px++) {
                a2[c2p * 16        + py * 4 + px] = fmaxf(fmaxf(m0[2*px], m0[2*px+1]), 0.0f);
                a2[(c2p + 16) * 16 + py * 4 + px] = fmaxf(fmaxf(m1[2*px], m1[2*px+1]), 0.0f);
            }
        }
    }
    __syncthreads();

    // ---------- dense 512 -> 10 (per image: 10 outputs x 8 lanes) ----------
    // WARP-UNIFORM: every thread runs the loop + shuffles (clamped output
    // index keeps addresses in-bounds); only (l==0 && o<10) writes.
    {
        const int o  = tl >> 3;               // 0..15
        const int oc = (o < 10) ? o : 9;      // clamp for safe addressing
        const int l  = tl & 7;
        const float* wrow = P + OFF_WD + oc * 512;
        const float* a2 = s_u + img * 512;
        float partial = 0.0f;
        #pragma unroll 8
        for (int f = l; f < 512; f += 8)
            partial = fmaf(wrow[f], a2[f], partial);
        #pragma unroll
        for (int off = 4; off; off >>= 1)
            partial += __shfl_down_sync(0xFFFFFFFFu, partial, off, 8);
        if (l == 0 && o < 10) s_dot[img][o] = partial + P[OFF_BD + o];
    }
    __syncthreads();

    // ---------- log_softmax over 10, write out ----------
    if (t < 64) {
        const int im = t >> 5;
        const int lane = t & 31;
        const float v = (lane < 10) ? s_dot[im][lane] : -INFINITY;
        float mx = v;
        #pragma unroll
        for (int off = 16; off; off >>= 1)
            mx = fmaxf(mx, __shfl_xor_sync(0xFFFFFFFFu, mx, off));
        const float e = (lane < 10) ? __expf(v - mx) : 0.0f;
        float s = e;
        #pragma unroll
        for (int off = 16; off; off >>= 1)
            s += __shfl_xor_sync(0xFFFFFFFFu, s, off);
        if (lane < 10) {
            const int n = npair * 2 + im;
            out[(init * BATCH_N + n) * 10 + lane] = v - mx - __logf(s);
        }
    }
}

extern "C" void kernel_launch(void* const* d_in, const int* in_sizes, int n_in,
                              void* d_out, int out_size)
{
    const float* params = (const float*)d_in[0];
    const float* batch  = (const float*)d_in[1];
    if (n_in >= 2 && in_sizes[0] != NUM_INITS * TOTAL_P) {
        params = (const float*)d_in[1];
        batch  = (const float*)d_in[0];
    }
    float* out = (float*)d_out;
    ensemble_lenet_kernel<<<NUM_INITS * (BATCH_N / 2), 256>>>(params, batch, out);
}